// round 12
// baseline (speedup 1.0000x reference)
#include <cuda_runtime.h>

#define IMG_H 4200
#define IMG_W 3200
#define HF 84
#define WF 64
#define NB 8
#define ROW_F2 (IMG_W / 2)           // 1600 float2 per image row
#define FEAT (NB * 2 * HF * WF)      // 86016
#define N_ROWS (NB * HF)             // 672 feature rows
#define ROW_DONE 640u                // 5 chunks x 128 finalizers

// conv1 partial sums per 10-row chunk: [chunk][n][ch][ty][tx]  (1.72 MB)
__device__ float g_part[5][FEAT];
// dynamic work queue + readiness flags (zero-init at load; reset by the LAST
// head block every launch, so every kernel_launch sees them zeroed)
__device__ unsigned g_tickets[5];
__device__ unsigned g_rowdone[N_ROWS];
__device__ unsigned g_headdone;

// ---------------------------------------------------------------------------
// Kernel 1: 50x50 stride-50 VALID conv, 1->2 ch (non-overlapping patches).
// R9's proven config: item = (chunk, feature row) = 10 consecutive image rows
// (128 KB contiguous); thread t<400 owns f2-cols {t,t+400,t+800,t+1200} with
// 10 float4 register weights; dynamic per-chunk tickets with prefetch
// (single wave, work-stealing absorbs CTA spread); ONE barrier per item.
// NEW: PDL trigger in the PROLOGUE (head starts immediately) + per-row
// release flags: finalizer stores -> __threadfence -> RED on g_rowdone[ri].
// ---------------------------------------------------------------------------
__global__ __launch_bounds__(416, 2) void conv1_kernel(const float* __restrict__ X,
                                                       const float* __restrict__ w)
{
    __shared__ float    s_part[2][2][1600];   // [buf][ch][f2col]  25.6 KB
    __shared__ unsigned s_ri[2];

    const int t = threadIdx.x;
    const bool active = (t < 400);
    const int chunk = blockIdx.x % 5;         // tile rows chunk*10 .. +9

    // register weights: rows chunk*10+r, f2-col t%25
    const float2* wv0 = (const float2*)w;           // ch0: 1250 f2
    const float2* wv1 = (const float2*)(w + 2500);  // ch1
    const int wc = active ? (t % 25) : 0;
    float4 wr[10];
#pragma unroll
    for (int r = 0; r < 10; r++) {
        const int wi = (chunk * 10 + r) * 25 + wc;
        const float2 p0 = active ? wv0[wi] : make_float2(0.f, 0.f);
        const float2 p1 = active ? wv1[wi] : make_float2(0.f, 0.f);
        wr[r] = make_float4(p0.x, p0.y, p1.x, p1.y);
    }

    cudaTriggerProgrammaticLaunchCompletion();   // let head co-launch NOW

    if (t == 0) s_ri[0] = atomicAdd(&g_tickets[chunk], 1u);
    __syncthreads();

#pragma unroll 1
    for (int j = 0; ; j++) {
        const int buf = j & 1;
        const unsigned ri = s_ri[buf];        // uniform across block
        if (ri >= N_ROWS) break;

        if (t == 0) s_ri[buf ^ 1] = atomicAdd(&g_tickets[chunk], 1u);  // prefetch

        const int n  = ri / HF;
        const int ty = ri % HF;

        if (active) {
            const float2* base = (const float2*)X
                + (size_t)n * (IMG_H * ROW_F2)
                + (size_t)(ty * 50 + chunk * 10) * ROW_F2
                + t;

            float a[8];                        // [colslot k][ch]
#pragma unroll
            for (int i = 0; i < 8; i++) a[i] = 0.f;

#pragma unroll
            for (int r = 0; r < 10; r++) {
#pragma unroll
                for (int k = 0; k < 4; k++) {
                    const float2 xv = __ldg(base + r * ROW_F2 + k * 400);
                    a[k * 2 + 0] += xv.x * wr[r].x + xv.y * wr[r].y;
                    a[k * 2 + 1] += xv.x * wr[r].z + xv.y * wr[r].w;
                }
            }
#pragma unroll
            for (int k = 0; k < 4; k++) {
                s_part[buf][0][t + k * 400] = a[k * 2 + 0];
                s_part[buf][1][t + k * 400] = a[k * 2 + 1];
            }
        }
        __syncthreads();   // s_part[buf] + next ticket ready; prev buf free

        // 128 finalizers; release: store -> fence -> RED (threadfence-
        // reduction pattern: each thread's fence orders ITS store before
        // ITS atomic; consumer sees count==640 => all 640 stores visible)
        if (t < 128) {
            const int ch = t >> 6, tile = t & 63;
            float s = 0.f;
#pragma unroll
            for (int m = 0; m < 25; m++) s += s_part[buf][ch][tile * 25 + m];
            g_part[chunk][((n * 2 + ch) * HF + ty) * WF + tile] = s;
            __threadfence();
            atomicAdd(&g_rowdone[ri], 1u);   // no return use -> RED
        }
    }
}

// ---------------------------------------------------------------------------
// Kernel 2: fused head (proven 128-thread shape, 336 blocks x 2 feature
// rows). Runs CONCURRENTLY with conv1: tid0 spin-waits (with nanosleep) on
// the 3-4 row flags this block needs, then fence + syncthreads (acquire).
// Staging sums the 5 chunk partials + bias. Last block resets all counters.
// ---------------------------------------------------------------------------
__global__ __launch_bounds__(128) void head_kernel(const float* __restrict__ conv_b,
                                                   const float* __restrict__ box_w,
                                                   const float* __restrict__ box_b,
                                                   const float* __restrict__ cls_w,
                                                   const float* __restrict__ cls_b,
                                                   float4* __restrict__ out)
{
    __shared__ float  s_bw[36 * 18];       // box_w [36,2,3,3]
    __shared__ float  s_bb[36];
    __shared__ float  s_cw[36];            // cls_w [2,2,3,3]
    __shared__ float  s_cb[2];
    __shared__ float  s_f[2][4][64];       // feats ch x rows(y0-1..y0+2) x cols
    __shared__ float4 s_stage[128 * 9];    // output staging (18 KB)
    __shared__ unsigned s_last;

    const int tid = threadIdx.x;

    for (int i = tid; i < 36 * 18; i += 128) s_bw[i] = box_w[i];
    if (tid < 36) {
        s_bb[tid] = box_b[tid];
        s_cw[tid] = cls_w[tid];
    }
    if (tid < 2) s_cb[tid] = cls_b[tid];

    const int n  = blockIdx.x / 42;
    const int y0 = (blockIdx.x % 42) * 2;   // block covers rows y0, y0+1
    const float cb0 = conv_b[0], cb1 = conv_b[1];

    // wait for the feature rows this block needs (fine-grained overlap)
    if (tid == 0) {
#pragma unroll
        for (int i = 0; i < 4; i++) {
            const int yy = y0 - 1 + i;
            if (yy >= 0 && yy < HF) {
                volatile unsigned* f = &g_rowdone[n * HF + yy];
                while (*f < ROW_DONE) __nanosleep(256);
            }
        }
        __threadfence();                    // acquire
    }
    __syncthreads();                        // propagate to all threads

    // stage feats rows y0-1 .. y0+2 (zero-padded): sum 5 partials + bias
#pragma unroll
    for (int i = 0; i < 4; i++) {
        const int e  = tid + i * 128;       // 0..511
        const int xx = e & 63;
        const int rr = (e >> 6) & 3;        // row y0-1+rr
        const int ic = e >> 8;
        const int yy = y0 - 1 + rr;
        float v = 0.0f;
        if (yy >= 0 && yy < HF) {
            const int idx = ((n * 2 + ic) * HF + yy) * WF + xx;
            v = ic ? cb1 : cb0;
#pragma unroll
            for (int c = 0; c < 5; c++) v += g_part[c][idx];
        }
        s_f[ic][rr][xx] = v;
    }
    __syncthreads();

    const int x  = tid & 63;
    const int ly = tid >> 6;                // 0 or 1
    const int y  = y0 + ly;

    // gather 3x3x2 neighborhood from smem (x edges zero-padded)
    float f[18];
#pragma unroll
    for (int ic = 0; ic < 2; ic++) {
#pragma unroll
        for (int dy = 0; dy < 3; dy++) {
#pragma unroll
            for (int dx = 0; dx < 3; dx++) {
                const int xx = x + dx - 1;
                float v = 0.0f;
                if (xx >= 0 && xx < WF) v = s_f[ic][ly + dy][xx];
                f[ic * 9 + dy * 3 + dx] = v;
            }
        }
    }

    // cls conv + 2-channel softmax threshold
    float c0 = s_cb[0], c1 = s_cb[1];
#pragma unroll
    for (int k = 0; k < 18; k++) {
        c0 += f[k] * s_cw[k];
        c1 += f[k] * s_cw[18 + k];
    }
    const float m  = fmaxf(c0, c1);
    const float e0 = __expf(c0 - m), e1 = __expf(c1 - m);
    const float p1 = e1 / (e0 + e1);
    const float mval = (p1 > 0.95f) ? 1.0f : 0.0f;

    const float gx = ((float)x + 0.5f) * 50.0f;
    const float gy = ((float)y + 0.5f) * 50.0f;
    const float SZ[3] = {16.0f, 32.0f, 64.0f};
    const float RI[3] = {0.70710678118654752f, 1.0f, 1.41421356237309505f};

#pragma unroll
    for (int a = 0; a < 9; a++) {
        float o0 = s_bb[a * 4 + 0], o1 = s_bb[a * 4 + 1];
        float o2 = s_bb[a * 4 + 2], o3 = s_bb[a * 4 + 3];
        const float* wp = &s_bw[a * 4 * 18];
#pragma unroll
        for (int kk = 0; kk < 18; kk++) {
            const float fv = f[kk];
            o0 += fv * wp[kk];
            o1 += fv * wp[18 + kk];
            o2 += fv * wp[36 + kk];
            o3 += fv * wp[54 + kk];
        }
        const float s  = SZ[a / 3];
        const float r  = RI[a % 3];
        const float wa = (s / r) * 0.5f;
        const float ha = (s * r) * 0.5f;
        float v0 = fminf(fmaxf(gx - wa + o0, 0.0f), (float)IMG_W);
        float v1 = fminf(fmaxf(gy - ha + o1, 0.0f), (float)IMG_H);
        float v2 = fminf(fmaxf(gx + wa + o2, 0.0f), (float)IMG_W);
        float v3 = fminf(fmaxf(gy + ha + o3, 0.0f), (float)IMG_H);
        s_stage[tid * 9 + a] =
            make_float4(v0 * mval, v1 * mval, v2 * mval, v3 * mval);
    }
    __syncthreads();

    // coalesced copy-out: block's 128 positions = 1152 contiguous float4
    float4* bout = out + (size_t)blockIdx.x * 128 * 9;
#pragma unroll
    for (int i = 0; i < 9; i++)
        bout[tid + 128 * i] = s_stage[tid + 128 * i];

    // last finished block resets all counters for the next launch
    if (tid == 0) s_last = atomicAdd(&g_headdone, 1u);
    __syncthreads();
    if (s_last == 335u) {
        for (int i = tid; i < N_ROWS; i += 128) g_rowdone[i] = 0u;
        if (tid < 5) g_tickets[tid] = 0u;
        if (tid == 0) g_headdone = 0u;
    }
}

extern "C" void kernel_launch(void* const* d_in, const int* in_sizes, int n_in,
                              void* d_out, int out_size)
{
    const float* X      = (const float*)d_in[0];
    const float* conv_w = (const float*)d_in[1];
    const float* conv_b = (const float*)d_in[2];
    const float* box_w  = (const float*)d_in[3];
    const float* box_b  = (const float*)d_in[4];
    const float* cls_w  = (const float*)d_in[5];
    const float* cls_b  = (const float*)d_in[6];
    float4* out = (float4*)d_out;

    // 295 blocks (59 per chunk) -- single wave, dynamic tickets
    conv1_kernel<<<295, 416>>>(X, conv_w);

    // head co-launches via PDL (conv1 triggers in its prologue); data deps
    // handled by per-row flags, so no grid-wide dependency sync needed
    cudaLaunchConfig_t cfg = {};
    cfg.gridDim  = dim3(336, 1, 1);
    cfg.blockDim = dim3(128, 1, 1);
    cfg.dynamicSmemBytes = 0;
    cfg.stream = 0;
    cudaLaunchAttribute attrs[1];
    attrs[0].id = cudaLaunchAttributeProgrammaticStreamSerialization;
    attrs[0].val.programmaticStreamSerializationAllowed = 1;
    cfg.attrs = attrs;
    cfg.numAttrs = 1;
    cudaLaunchKernelEx(&cfg, head_kernel, conv_b, box_w, box_b, cls_w, cls_b, out);
}

// round 13
// speedup vs baseline: 1.1163x; 1.1163x over previous
#include <cuda_runtime.h>

#define IMG_H 4200
#define IMG_W 3200
#define HF 84
#define WF 64
#define NB 8
#define ROW_F2 (IMG_W / 2)           // 1600 float2 per image row
#define FEAT (NB * 2 * HF * WF)      // 86016
#define N_ROWS (NB * HF)             // 672 feature rows

// conv1 partial sums per 10-row chunk: [chunk][n][ch][ty][tx]  (1.72 MB)
__device__ float g_part[5][FEAT];
// dynamic work queue: one ticket counter per weight-chunk.
// Zero-initialized at load; reset by head_kernel (after gridsync, conv1 is
// provably done) so the invariant "tickets == 0 on entry" holds every launch.
__device__ unsigned g_tickets[5];

// ---------------------------------------------------------------------------
// Kernel 1: 50x50 stride-50 VALID conv, 1->2 ch (non-overlapping patches).
// BEST MEASURED CONFIG (R9, ~76.7us): item = (chunk, feature row) = 10
// consecutive image rows (128 KB contiguous); thread t<400 owns f2-cols
// {t,t+400,t+800,t+1200} with 10 float4 register weights; dynamic per-chunk
// tickets with prefetch (295 blocks = single wave; work-stealing absorbs
// per-CTA spread); ONE double-buffered barrier per item.
// ---------------------------------------------------------------------------
__global__ __launch_bounds__(416, 2) void conv1_kernel(const float* __restrict__ X,
                                                       const float* __restrict__ w)
{
    __shared__ float    s_part[2][2][1600];   // [buf][ch][f2col]  25.6 KB
    __shared__ unsigned s_ri[2];

    const int t = threadIdx.x;
    const bool active = (t < 400);
    const int chunk = blockIdx.x % 5;         // tile rows chunk*10 .. +9

    // register weights: rows chunk*10+r, f2-col t%25
    const float2* wv0 = (const float2*)w;           // ch0: 1250 f2
    const float2* wv1 = (const float2*)(w + 2500);  // ch1
    const int wc = active ? (t % 25) : 0;
    float4 wr[10];
#pragma unroll
    for (int r = 0; r < 10; r++) {
        const int wi = (chunk * 10 + r) * 25 + wc;
        const float2 p0 = active ? wv0[wi] : make_float2(0.f, 0.f);
        const float2 p1 = active ? wv1[wi] : make_float2(0.f, 0.f);
        wr[r] = make_float4(p0.x, p0.y, p1.x, p1.y);
    }

    if (t == 0) s_ri[0] = atomicAdd(&g_tickets[chunk], 1u);
    __syncthreads();

#pragma unroll 1
    for (int j = 0; ; j++) {
        const int buf = j & 1;
        const unsigned ri = s_ri[buf];        // uniform across block
        if (ri >= N_ROWS) break;

        if (t == 0) s_ri[buf ^ 1] = atomicAdd(&g_tickets[chunk], 1u);  // prefetch

        const int n  = ri / HF;
        const int ty = ri % HF;

        if (active) {
            const float2* base = (const float2*)X
                + (size_t)n * (IMG_H * ROW_F2)
                + (size_t)(ty * 50 + chunk * 10) * ROW_F2
                + t;

            float a[8];                        // [colslot k][ch]
#pragma unroll
            for (int i = 0; i < 8; i++) a[i] = 0.f;

#pragma unroll
            for (int r = 0; r < 10; r++) {
#pragma unroll
                for (int k = 0; k < 4; k++) {
                    const float2 xv = __ldg(base + r * ROW_F2 + k * 400);
                    a[k * 2 + 0] += xv.x * wr[r].x + xv.y * wr[r].y;
                    a[k * 2 + 1] += xv.x * wr[r].z + xv.y * wr[r].w;
                }
            }
#pragma unroll
            for (int k = 0; k < 4; k++) {
                s_part[buf][0][t + k * 400] = a[k * 2 + 0];
                s_part[buf][1][t + k * 400] = a[k * 2 + 1];
            }
        }
        __syncthreads();   // s_part[buf] + next ticket ready; prev buf free

        // 128 finalizers: ch = t>>6, tile = t&63 (stride-25 smem reads are
        // bank-clean; 64-float coalesced g_part stores)
        if (t < 128) {
            const int ch = t >> 6, tile = t & 63;
            float s = 0.f;
#pragma unroll
            for (int m = 0; m < 25; m++) s += s_part[buf][ch][tile * 25 + m];
            g_part[chunk][((n * 2 + ch) * HF + ty) * WF + tile] = s;
        }
    }
    cudaTriggerProgrammaticLaunchCompletion();
}

// ---------------------------------------------------------------------------
// Kernel 2: fused head. BEST MEASURED SHAPE (R7, 11.3us): 336 blocks x 128
// threads, block = 2 feature rows. PDL: weight prologue overlaps conv1's
// drain; gridsync before touching g_part; staging sums the 5 chunk partials
// + bias; warp-staged smem -> fully coalesced float4 stores. Also resets the
// work-queue tickets for the next launch.
// ---------------------------------------------------------------------------
__global__ __launch_bounds__(128) void head_kernel(const float* __restrict__ conv_b,
                                                   const float* __restrict__ box_w,
                                                   const float* __restrict__ box_b,
                                                   const float* __restrict__ cls_w,
                                                   const float* __restrict__ cls_b,
                                                   float4* __restrict__ out)
{
    __shared__ float  s_bw[36 * 18];       // box_w [36,2,3,3]
    __shared__ float  s_bb[36];
    __shared__ float  s_cw[36];            // cls_w [2,2,3,3]
    __shared__ float  s_cb[2];
    __shared__ float  s_f[2][4][64];       // feats ch x rows(y0-1..y0+2) x cols
    __shared__ float4 s_stage[128 * 9];    // output staging (18 KB)

    const int tid = threadIdx.x;

    for (int i = tid; i < 36 * 18; i += 128) s_bw[i] = box_w[i];
    if (tid < 36) {
        s_bb[tid] = box_b[tid];
        s_cw[tid] = cls_w[tid];
    }
    if (tid < 2) s_cb[tid] = cls_b[tid];

    const int n  = blockIdx.x / 42;
    const int y0 = (blockIdx.x % 42) * 2;   // block covers rows y0, y0+1
    const float cb0 = conv_b[0], cb1 = conv_b[1];

    cudaGridDependencySynchronize();        // conv1's g_part now visible

    // reset work-queue tickets for the next launch (conv1 provably done)
    if (blockIdx.x == 0 && tid < 5) g_tickets[tid] = 0;

    // stage feats rows y0-1 .. y0+2 (zero-padded): sum 5 partials + bias
#pragma unroll
    for (int i = 0; i < 4; i++) {
        const int e  = tid + i * 128;       // 0..511
        const int xx = e & 63;
        const int rr = (e >> 6) & 3;        // row y0-1+rr
        const int ic = e >> 8;
        const int yy = y0 - 1 + rr;
        float v = 0.0f;
        if (yy >= 0 && yy < HF) {
            const int idx = ((n * 2 + ic) * HF + yy) * WF + xx;
            v = ic ? cb1 : cb0;
#pragma unroll
            for (int c = 0; c < 5; c++) v += g_part[c][idx];
        }
        s_f[ic][rr][xx] = v;
    }
    __syncthreads();

    const int x  = tid & 63;
    const int ly = tid >> 6;                // 0 or 1
    const int y  = y0 + ly;

    // gather 3x3x2 neighborhood from smem (x edges zero-padded)
    float f[18];
#pragma unroll
    for (int ic = 0; ic < 2; ic++) {
#pragma unroll
        for (int dy = 0; dy < 3; dy++) {
#pragma unroll
            for (int dx = 0; dx < 3; dx++) {
                const int xx = x + dx - 1;
                float v = 0.0f;
                if (xx >= 0 && xx < WF) v = s_f[ic][ly + dy][xx];
                f[ic * 9 + dy * 3 + dx] = v;
            }
        }
    }

    // cls conv + 2-channel softmax threshold
    float c0 = s_cb[0], c1 = s_cb[1];
#pragma unroll
    for (int k = 0; k < 18; k++) {
        c0 += f[k] * s_cw[k];
        c1 += f[k] * s_cw[18 + k];
    }
    const float m  = fmaxf(c0, c1);
    const float e0 = __expf(c0 - m), e1 = __expf(c1 - m);
    const float p1 = e1 / (e0 + e1);
    const float mval = (p1 > 0.95f) ? 1.0f : 0.0f;

    const float gx = ((float)x + 0.5f) * 50.0f;
    const float gy = ((float)y + 0.5f) * 50.0f;
    const float SZ[3] = {16.0f, 32.0f, 64.0f};
    const float RI[3] = {0.70710678118654752f, 1.0f, 1.41421356237309505f};

#pragma unroll
    for (int a = 0; a < 9; a++) {
        float o0 = s_bb[a * 4 + 0], o1 = s_bb[a * 4 + 1];
        float o2 = s_bb[a * 4 + 2], o3 = s_bb[a * 4 + 3];
        const float* wp = &s_bw[a * 4 * 18];
#pragma unroll
        for (int kk = 0; kk < 18; kk++) {
            const float fv = f[kk];
            o0 += fv * wp[kk];
            o1 += fv * wp[18 + kk];
            o2 += fv * wp[36 + kk];
            o3 += fv * wp[54 + kk];
        }
        const float s  = SZ[a / 3];
        const float r  = RI[a % 3];
        const float wa = (s / r) * 0.5f;
        const float ha = (s * r) * 0.5f;
        float v0 = fminf(fmaxf(gx - wa + o0, 0.0f), (float)IMG_W);
        float v1 = fminf(fmaxf(gy - ha + o1, 0.0f), (float)IMG_H);
        float v2 = fminf(fmaxf(gx + wa + o2, 0.0f), (float)IMG_W);
        float v3 = fminf(fmaxf(gy + ha + o3, 0.0f), (float)IMG_H);
        s_stage[tid * 9 + a] =
            make_float4(v0 * mval, v1 * mval, v2 * mval, v3 * mval);
    }
    __syncthreads();

    // coalesced copy-out: block's 128 positions = 1152 contiguous float4
    float4* bout = out + (size_t)blockIdx.x * 128 * 9;
#pragma unroll
    for (int i = 0; i < 9; i++)
        bout[tid + 128 * i] = s_stage[tid + 128 * i];
}

extern "C" void kernel_launch(void* const* d_in, const int* in_sizes, int n_in,
                              void* d_out, int out_size)
{
    const float* X      = (const float*)d_in[0];
    const float* conv_w = (const float*)d_in[1];
    const float* conv_b = (const float*)d_in[2];
    const float* box_w  = (const float*)d_in[3];
    const float* box_b  = (const float*)d_in[4];
    const float* cls_w  = (const float*)d_in[5];
    const float* cls_b  = (const float*)d_in[6];
    float4* out = (float4*)d_out;

    // 295 blocks (59 per chunk) -- single wave, dynamic tickets
    conv1_kernel<<<295, 416>>>(X, conv_w);

    // head with programmatic dependent launch (prologue overlaps conv1 drain)
    cudaLaunchConfig_t cfg = {};
    cfg.gridDim  = dim3(336, 1, 1);
    cfg.blockDim = dim3(128, 1, 1);
    cfg.dynamicSmemBytes = 0;
    cfg.stream = 0;
    cudaLaunchAttribute attrs[1];
    attrs[0].id = cudaLaunchAttributeProgrammaticStreamSerialization;
    attrs[0].val.programmaticStreamSerializationAllowed = 1;
    cfg.attrs = attrs;
    cfg.numAttrs = 1;
    cudaLaunchKernelEx(&cfg, head_kernel, conv_b, box_w, box_b, cls_w, cls_b, out);
}